// round 3
// baseline (speedup 1.0000x reference)
#include <cuda_runtime.h>
#include <cuda_bf16.h>

// Nearest-codeword quantization, uniform sorted 16-entry codebook.
// out[i] = argmin_c |x[i] - c|, tie toward the LOWER codeword
// (matches reference: pick_lo = |x - c_lo| <= |x - c_hi|).
//
// R3 changes vs R2:
//  - smem PAIR table (float2 {c[k], c[k+1]}): ONE LDS.64 per element instead
//    of two LDS.32 -> half the shared-memory wavefronts (L1 was 67%).
//  - ILP=4: four independent float4 LDGs issued back-to-back per thread
//    (MLP_p1=4) to hide DRAM latency better (issue was 35%, DRAM 69%).
// Classification still uses the TRUE codebook values -> bit-exact vs reference.

#define K_CB 16

__global__ void __launch_bounds__(256)
quant_uniform_kernel(const float4* __restrict__ x,
                     const float*  __restrict__ cb,
                     float4* __restrict__ out,
                     int n4)
{
    __shared__ float2 s_pair[K_CB - 1];   // {c[k], c[k+1]}, k = 0..14
    __shared__ float  s_c0, s_c15;
    if (threadIdx.x < K_CB - 1) {
        float a = cb[threadIdx.x];
        float b = cb[threadIdx.x + 1];
        s_pair[threadIdx.x] = make_float2(a, b);
        if (threadIdx.x == 0)  s_c0  = a;
        if (threadIdx.x == K_CB - 2) s_c15 = b;
    }
    __syncthreads();

    const float c0 = s_c0;
    const float inv_step = (float)(K_CB - 1) / (s_c15 - c0);

    int base = (blockIdx.x * blockDim.x + threadIdx.x) * 4;

    if (base + 3 < n4) {
        // Fast path: batch 4 independent 16B loads first (MLP_p1 = 4).
        float4 v0 = x[base + 0];
        float4 v1 = x[base + 1];
        float4 v2 = x[base + 2];
        float4 v3 = x[base + 3];

        float4 vv[4] = {v0, v1, v2, v3};
        float4 rr[4];

#pragma unroll
        for (int u = 0; u < 4; u++) {
            float* vp = reinterpret_cast<float*>(&vv[u]);
            float* rp = reinterpret_cast<float*>(&rr[u]);
#pragma unroll
            for (int j = 0; j < 4; j++) {
                float xv = vp[j];
                int k = __float2int_rd((xv - c0) * inv_step);
                k = max(0, min(k, K_CB - 2));
                float2 p = s_pair[k];            // one LDS.64
                rp[j] = (fabsf(xv - p.x) <= fabsf(xv - p.y)) ? p.x : p.y;
            }
        }

        out[base + 0] = rr[0];
        out[base + 1] = rr[1];
        out[base + 2] = rr[2];
        out[base + 3] = rr[3];
    } else {
        // Tail (not taken for 8192x8192, kept for generality).
        for (int idx = base; idx < n4; idx++) {
            float4 v = x[idx];
            float4 r;
            float* vp = reinterpret_cast<float*>(&v);
            float* rp = reinterpret_cast<float*>(&r);
#pragma unroll
            for (int j = 0; j < 4; j++) {
                float xv = vp[j];
                int k = __float2int_rd((xv - c0) * inv_step);
                k = max(0, min(k, K_CB - 2));
                float2 p = s_pair[k];
                rp[j] = (fabsf(xv - p.x) <= fabsf(xv - p.y)) ? p.x : p.y;
            }
            out[idx] = r;
        }
    }
}

extern "C" void kernel_launch(void* const* d_in, const int* in_sizes, int n_in,
                              void* d_out, int out_size)
{
    const float* x  = (const float*)d_in[0];
    const float* cb = (const float*)d_in[1];
    float* out = (float*)d_out;

    int n = in_sizes[0];          // 8192*8192 = 67,108,864
    int n4 = n >> 2;              // 16,777,216 float4

    const int threads = 256;
    const int per_block = threads * 4;                 // 1024 float4 per block
    int blocks = (n4 + per_block - 1) / per_block;     // 16384

    quant_uniform_kernel<<<blocks, threads>>>(
        (const float4*)x, cb, (float4*)out, n4);
}

// round 4
// speedup vs baseline: 1.0617x; 1.0617x over previous
#include <cuda_runtime.h>
#include <cuda_bf16.h>

// Nearest-codeword quantization, uniform sorted 16-entry codebook.
// out[i] = argmin_c |x[i] - c|, tie toward the LOWER codeword
// (matches reference: pick_lo = |x - c_lo| <= |x - c_hi|).
//
// R4: ONE dynamic LDS per element (was 2). m = round((x-c0)*inv_step) is the
// nearest index except within a few ulp of a midpoint; a guard band EPS=1e-4
// in index space (>=30x the worst-case fp error ~3e-6) routes those rare
// elements (~2e-4 probability) to an exact two-value comparison, so the
// output is still bit-exact vs the reference. Loads batched up-front (MLP=4),
// streaming cache hints (no reuse).

#define K_CB 16

__global__ void __launch_bounds__(256)
quant_uniform_kernel(const float4* __restrict__ x,
                     const float*  __restrict__ cb,
                     float4* __restrict__ out,
                     int n4)
{
    __shared__ float s_cb[K_CB];
    if (threadIdx.x < K_CB) s_cb[threadIdx.x] = cb[threadIdx.x];
    __syncthreads();

    const float c0 = s_cb[0];
    const float inv_step = (float)(K_CB - 1) / (s_cb[K_CB - 1] - c0);
    const float b0 = -c0 * inv_step;
    const float EPS = 1e-4f;           // index-space guard band

    int base = (blockIdx.x * blockDim.x + threadIdx.x) * 4;

    if (base + 3 < n4) {
        // Batch 4 independent 16B loads (MLP_p1 = 4), streaming hint.
        float4 v[4];
        v[0] = __ldcs(x + base + 0);
        v[1] = __ldcs(x + base + 1);
        v[2] = __ldcs(x + base + 2);
        v[3] = __ldcs(x + base + 3);

#pragma unroll
        for (int u = 0; u < 4; u++) {
            float4 r;
            float* vp = reinterpret_cast<float*>(&v[u]);
            float* rp = reinterpret_cast<float*>(&r);
#pragma unroll
            for (int j = 0; j < 4; j++) {
                float xv = vp[j];
                float t  = fmaf(xv, inv_step, b0);
                int   m  = __float2int_rn(t);
                int   mc = min(max(m, 0), K_CB - 1);
                float d  = t - (float)m;

                float val = s_cb[mc];                       // single LDS
                // Rare exact path: only when t is within EPS of a half-integer
                // AND inside the table range.
                if (!((m != mc) | (fabsf(d) < (0.5f - EPS)))) {
                    int k = min(max(__float2int_rd(t), 0), K_CB - 2);
                    float lo = s_cb[k];
                    float hi = s_cb[k + 1];
                    val = (fabsf(xv - lo) <= fabsf(xv - hi)) ? lo : hi;
                }
                rp[j] = val;
            }
            __stcs(out + base + u, r);    // store per-u: caps live registers
        }
    } else {
        // Tail (not taken for 8192x8192).
        for (int idx = base; idx < n4 && idx >= 0; idx++) {
            float4 v = __ldcs(x + idx);
            float4 r;
            float* vp = reinterpret_cast<float*>(&v);
            float* rp = reinterpret_cast<float*>(&r);
#pragma unroll
            for (int j = 0; j < 4; j++) {
                float xv = vp[j];
                float t  = fmaf(xv, inv_step, b0);
                int   m  = __float2int_rn(t);
                int   mc = min(max(m, 0), K_CB - 1);
                float d  = t - (float)m;
                float val = s_cb[mc];
                if (!((m != mc) | (fabsf(d) < (0.5f - EPS)))) {
                    int k = min(max(__float2int_rd(t), 0), K_CB - 2);
                    float lo = s_cb[k];
                    float hi = s_cb[k + 1];
                    val = (fabsf(xv - lo) <= fabsf(xv - hi)) ? lo : hi;
                }
                rp[j] = val;
            }
            __stcs(out + idx, r);
        }
    }
}

extern "C" void kernel_launch(void* const* d_in, const int* in_sizes, int n_in,
                              void* d_out, int out_size)
{
    const float* x  = (const float*)d_in[0];
    const float* cb = (const float*)d_in[1];
    float* out = (float*)d_out;

    int n  = in_sizes[0];         // 8192*8192 = 67,108,864
    int n4 = n >> 2;              // 16,777,216 float4

    const int threads = 256;
    const int per_block = threads * 4;                 // 1024 float4 / block
    int blocks = (n4 + per_block - 1) / per_block;     // 16384

    quant_uniform_kernel<<<blocks, threads>>>(
        (const float4*)x, cb, (float4*)out, n4);
}